// round 7
// baseline (speedup 1.0000x reference)
#include <cuda_runtime.h>
#include <math.h>
#include <cstdint>

#define T_LEN   16384
#define NATOMS  512
#define ALEN    512
#define BATCH   8
#define NBLK    16
#define BLKSZ   1024
#define SIGL    1536
#define N_ITER  32
#define EPS_N   1e-8f

#define TM 128                 // atoms per CTA tile
#define KC 64                  // K chunk
#define NCHUNK (ALEN / KC)     // 8
#define APAD 68                // padded a-stride in smem
#define SSTR_MAX 648           // padded signal split stride (TNP=128)
#define SMEM_BYTES ((4 * TM * APAD + 2 * SSTR_MAX) * 4)   // 144448 B

// ---------------- device-global scratch ----------------
__device__ float g_dn[NATOMS * ALEN];
__device__ __align__(16) uint32_t g_dtf[2 * NATOMS * ALEN];   // tf32 big/small splits of dn
__device__ float g_fm[(size_t)BATCH * NATOMS * T_LEN];        // 256 MB
__device__ float g_bmax[BATCH * NATOMS * NBLK];
__device__ int   g_barg[BATCH * NATOMS * NBLK];
__device__ float g_sig[BATCH * SIGL];
__device__ float g_selv[BATCH];
__device__ int   g_seln[BATCH];
__device__ int   g_selt[BATCH];

// ---------------- helpers ----------------
__device__ __forceinline__ uint32_t f2tf32(float v) {
    uint32_t r;
    asm("cvt.rna.tf32.f32 %0, %1;" : "=r"(r) : "f"(v));
    return r;
}
__device__ __forceinline__ void mma8(float* c, const uint32_t* a, const uint32_t* b) {
    asm volatile(
        "mma.sync.aligned.m16n8k8.row.col.f32.tf32.tf32.f32 "
        "{%0,%1,%2,%3}, {%4,%5,%6,%7}, {%8,%9}, {%0,%1,%2,%3};"
        : "+f"(c[0]), "+f"(c[1]), "+f"(c[2]), "+f"(c[3])
        : "r"(a[0]), "r"(a[1]), "r"(a[2]), "r"(a[3]), "r"(b[0]), "r"(b[1]));
}
#define CP_COMMIT() asm volatile("cp.async.commit_group;" ::: "memory")
#define CP_WAIT0()  asm volatile("cp.async.wait_group 0;" ::: "memory")
#define CP_WAIT1()  asm volatile("cp.async.wait_group 1;" ::: "memory")

// async-stage one dict chunk (both tf32 splits) into an smem buffer
__device__ __forceinline__ void stage_chunk_async(uint32_t* sAbuf, int n0, int a0, int tid) {
    #pragma unroll
    for (int e = tid; e < TM * 16; e += 256) {
        int kq = e & 15, n = e >> 4;
        size_t gi = (size_t)(n0 + n) * ALEN + a0 + kq * 4;
        uint32_t d0 = (uint32_t)__cvta_generic_to_shared(&sAbuf[n * APAD + kq * 4]);
        uint32_t d1 = (uint32_t)__cvta_generic_to_shared(&sAbuf[TM * APAD + n * APAD + kq * 4]);
        asm volatile("cp.async.cg.shared.global [%0], [%1], 16;" :: "r"(d0), "l"(&g_dtf[gi]) : "memory");
        asm volatile("cp.async.cg.shared.global [%0], [%1], 16;" :: "r"(d1), "l"(&g_dtf[NATOMS * ALEN + gi]) : "memory");
    }
}

// ---------------- dictionary normalization ----------------
__global__ void k_norm(const float* __restrict__ d) {
    int n = blockIdx.x;
    int tid = threadIdx.x;
    __shared__ float red[256];
    float s = 0.f;
    for (int a = tid; a < ALEN; a += 256) { float v = d[n * ALEN + a]; s += v * v; }
    red[tid] = s; __syncthreads();
    for (int st = 128; st > 0; st >>= 1) {
        if (tid < st) red[tid] += red[tid + st];
        __syncthreads();
    }
    float inv = 1.0f / (sqrtf(red[0]) + EPS_N);
    for (int a = tid; a < ALEN; a += 256) g_dn[n * ALEN + a] = d[n * ALEN + a] * inv;
}

// ---------------- precompute tf32 splits of the dictionary ----------------
__global__ void k_prep() {
    int n = blockIdx.x;
    for (int a = threadIdx.x; a < ALEN; a += 256) {
        float v = g_dn[n * ALEN + a];
        uint32_t big = f2tf32(v);
        float rem = v - __uint_as_float(big);
        g_dtf[n * ALEN + a] = big;
        g_dtf[NATOMS * ALEN + n * ALEN + a] = f2tf32(rem);
    }
}

// ---------------- output init ----------------
__global__ void k_init_out(const float* __restrict__ x, float* __restrict__ out) {
    int i = blockIdx.x * blockDim.x + threadIdx.x;
    int n = BATCH * T_LEN;
    if (i < n) { out[i] = x[i]; out[n + i] = 0.f; }
}

// ---------------- tensor-core correlation (3xTF32, cp.async double-buffered) ----------------
// fm[n, t] = sum_a dn[n,a] * sig[t + a]
// CTA: 128(n) x TNP(t). 8 warps = 2(m) x 4(n-col); warp tile 64(n) x TNP/4(t).
template<int TNP, bool DELTA>
__global__ __launch_bounds__(256, 1) void k_tconv(const float* __restrict__ x) {
    constexpr int NI = TNP / 32;              // B frags per warp
    constexpr int SWIN = TNP + ALEN;          // staged window (TNP+511 used)
    constexpr int SSTR = SWIN + 8;
    extern __shared__ __align__(16) uint32_t sm[];
    uint32_t* sA = sm;                        // [2 bufs][2 splits][TM][APAD]
    uint32_t* sS = sm + 4 * TM * APAD;        // [2 splits][SSTR]

    const int b  = blockIdx.z;
    const int n0 = blockIdx.y * TM;
    const int t0 = blockIdx.x * TNP;
    const int tid = threadIdx.x;
    const int wid = tid >> 5;
    const int lane = tid & 31;
    const int wm = wid & 1;
    const int wn = wid >> 1;
    const int g = lane >> 2;
    const int tig = lane & 3;

    const float* sig;
    int siglen, off;
    unsigned cmask = (1u << NCHUNK) - 1u;
    if (DELTA) {
        int tsel = g_selt[b];
        off = tsel - (ALEN - 1);
        if (off + t0 >= T_LEN || off + t0 + TNP - 1 < 0) return;
        int L = min(tsel + ALEN, T_LEN - 1) - tsel;
        if (L <= 0) return;
        sig = g_sig + b * SIGL;
        siglen = SIGL;
        cmask = 0;
        for (int c = 0; c < NCHUNK; c++) {
            int lo = t0 + c * KC;
            int hi = lo + (TNP - 1) + (KC - 1);
            if (lo < (ALEN - 1) + L && hi >= (ALEN - 1)) cmask |= 1u << c;
        }
        if (!cmask) return;
    } else {
        off = 0;
        sig = x + (size_t)b * T_LEN;
        siglen = T_LEN;
    }

    int clist[NCHUNK];
    int ncl = 0;
    for (int c = 0; c < NCHUNK; c++)
        if ((cmask >> c) & 1) clist[ncl++] = c;

    // kick off first dict chunk, then stage signal splits (overlapped)
    stage_chunk_async(sA, n0, clist[0] * KC, tid);
    CP_COMMIT();

    for (int i = tid; i < SWIN; i += 256) {
        int gi = t0 + i;
        float v = (gi < siglen) ? sig[gi] : 0.f;
        uint32_t big = f2tf32(v);
        float rem = v - __uint_as_float(big);
        sS[i] = big;
        sS[SSTR + i] = f2tf32(rem);
    }

    float acc[4][NI][4];
    #pragma unroll
    for (int mi = 0; mi < 4; mi++)
        #pragma unroll
        for (int ni = 0; ni < NI; ni++)
            #pragma unroll
            for (int q = 0; q < 4; q++) acc[mi][ni][q] = 0.f;

    for (int i = 0; i < ncl; i++) {
        if (i + 1 < ncl) {
            stage_chunk_async(sA + ((i + 1) & 1) * 2 * TM * APAD, n0, clist[i + 1] * KC, tid);
            CP_COMMIT();
            CP_WAIT1();
        } else {
            CP_WAIT0();
        }
        __syncthreads();     // chunk i visible to all (also covers sS on i=0)

        const uint32_t* base = sA + (i & 1) * 2 * TM * APAD;
        const int a0 = clist[i] * KC;

        #pragma unroll
        for (int kk = 0; kk < KC / 8; kk++) {
            const int col = kk * 8 + tig;
            uint32_t Ab[4][4], As[4][4], Bb[NI][2], Bs[NI][2];
            #pragma unroll
            for (int mi = 0; mi < 4; mi++) {
                int rm = wm * 64 + mi * 16 + g;
                const uint32_t* p = &base[rm * APAD + col];
                Ab[mi][0] = p[0];
                Ab[mi][1] = p[8 * APAD];
                Ab[mi][2] = p[4];
                Ab[mi][3] = p[8 * APAD + 4];
                const uint32_t* q = p + TM * APAD;
                As[mi][0] = q[0];
                As[mi][1] = q[8 * APAD];
                As[mi][2] = q[4];
                As[mi][3] = q[8 * APAD + 4];
            }
            #pragma unroll
            for (int ni = 0; ni < NI; ni++) {
                int idx = wn * (TNP / 4) + ni * 8 + g + a0 + col;
                Bb[ni][0] = sS[idx];
                Bb[ni][1] = sS[idx + 4];
                Bs[ni][0] = sS[SSTR + idx];
                Bs[ni][1] = sS[SSTR + idx + 4];
            }
            #pragma unroll
            for (int mi = 0; mi < 4; mi++)
                #pragma unroll
                for (int ni = 0; ni < NI; ni++) {
                    mma8(acc[mi][ni], As[mi], Bb[ni]);
                    mma8(acc[mi][ni], Ab[mi], Bs[ni]);
                    mma8(acc[mi][ni], Ab[mi], Bb[ni]);
                }
        }
        __syncthreads();     // MMA(i) done before buffer reuse at i+2
    }

    // epilogue
    #pragma unroll
    for (int mi = 0; mi < 4; mi++) {
        int n1 = n0 + wm * 64 + mi * 16 + g;
        float* row1 = g_fm + ((size_t)(b * NATOMS + n1)) * T_LEN;
        float* row2 = row1 + 8 * (size_t)T_LEN;
        #pragma unroll
        for (int ni = 0; ni < NI; ni++) {
            int tc = t0 + wn * (TNP / 4) + ni * 8 + tig * 2;
            if (!DELTA) {
                *(float2*)(row1 + tc) = make_float2(acc[mi][ni][0], acc[mi][ni][1]);
                *(float2*)(row2 + tc) = make_float2(acc[mi][ni][2], acc[mi][ni][3]);
            } else {
                int t = off + tc;
                if (t >= 0 && t < T_LEN)         row1[t]     -= acc[mi][ni][0];
                if (t + 1 >= 0 && t + 1 < T_LEN) row1[t + 1] -= acc[mi][ni][1];
                if (t >= 0 && t < T_LEN)         row2[t]     -= acc[mi][ni][2];
                if (t + 1 >= 0 && t + 1 < T_LEN) row2[t + 1] -= acc[mi][ni][3];
            }
        }
    }
}

// ---------------- block-max maintenance ----------------
__device__ void scan_block_body(int b, int n, int bl) {
    const float* row = &g_fm[((size_t)(b * NATOMS + n)) * T_LEN + bl * BLKSZ];
    int tid = threadIdx.x;
    float4 v = *reinterpret_cast<const float4*>(&row[tid * 4]);
    float bv = v.x; int bt = tid * 4;
    if (v.y > bv) { bv = v.y; bt = tid * 4 + 1; }
    if (v.z > bv) { bv = v.z; bt = tid * 4 + 2; }
    if (v.w > bv) { bv = v.w; bt = tid * 4 + 3; }
    __shared__ float sv[256];
    __shared__ int   st[256];
    sv[tid] = bv; st[tid] = bt;
    __syncthreads();
    for (int s = 128; s > 0; s >>= 1) {
        if (tid < s) {
            if (sv[tid + s] > sv[tid] || (sv[tid + s] == sv[tid] && st[tid + s] < st[tid])) {
                sv[tid] = sv[tid + s]; st[tid] = st[tid + s];
            }
        }
        __syncthreads();
    }
    if (tid == 0) {
        int idx = (b * NATOMS + n) * NBLK + bl;
        g_bmax[idx] = sv[0];
        g_barg[idx] = bl * BLKSZ + st[0];
    }
}

__global__ __launch_bounds__(256) void k_bmax_init() {
    scan_block_body(blockIdx.z, blockIdx.y, blockIdx.x);
}

__global__ __launch_bounds__(256) void k_refresh() {
    int b = blockIdx.z, n = blockIdx.y;
    int t = g_selt[b];
    int lo = max(0, t - (ALEN - 1));
    int hi = min(T_LEN - 1, t + (ALEN - 1));
    int bl0 = lo >> 10, bl1 = hi >> 10;
    if (blockIdx.x == 1 && bl1 == bl0) return;
    int bl = (blockIdx.x == 0) ? bl0 : bl1;
    scan_block_body(b, n, bl);
}

// ---------------- fused select + apply ----------------
__global__ __launch_bounds__(512) void k_select_apply(float* __restrict__ out) {
    int b = blockIdx.x;
    int tid = threadIdx.x;
    float bv = -3.402823466e38f;
    int   bf = 0x7FFFFFFF;
    const float* bm = &g_bmax[b * NATOMS * NBLK];
    const int*   ba = &g_barg[b * NATOMS * NBLK];
    for (int idx = tid; idx < NATOMS * NBLK; idx += 512) {
        float v = bm[idx];
        int flat = (idx >> 4) * T_LEN + ba[idx];
        if (v > bv || (v == bv && flat < bf)) { bv = v; bf = flat; }
    }
    __shared__ float sv[512];
    __shared__ int   sf[512];
    sv[tid] = bv; sf[tid] = bf;
    __syncthreads();
    for (int s = 256; s > 0; s >>= 1) {
        if (tid < s) {
            if (sv[tid + s] > sv[tid] || (sv[tid + s] == sv[tid] && sf[tid + s] < sf[tid])) {
                sv[tid] = sv[tid + s]; sf[tid] = sf[tid + s];
            }
        }
        __syncthreads();
    }
    float v = sv[0];
    int n = sf[0] >> 14;
    int t = sf[0] & (T_LEN - 1);
    if (tid == 0) {
        g_selv[b] = v;
        g_seln[b] = n;
        g_selt[b] = t;
    }
    int end = min(t + ALEN, T_LEN - 1);   // ref clips: position T-1 never written
    int L = end - t;
    float* res = out + (size_t)b * T_LEN;
    float* rec = out + (size_t)(BATCH + b) * T_LEN;
    if (tid < L) {
        float w = v * g_dn[n * ALEN + tid];
        res[t + tid] -= w;
        rec[t + tid] += w;
    }
    for (int u = tid; u < SIGL; u += 512) {
        int j = u - (ALEN - 1);
        g_sig[b * SIGL + u] = (j >= 0 && j < L) ? v * g_dn[n * ALEN + j] : 0.f;
    }
}

// ---------------- launch ----------------
extern "C" void kernel_launch(void* const* d_in, const int* in_sizes, int n_in,
                              void* d_out, int out_size) {
    const float* x = (const float*)d_in[0];
    const float* d = (const float*)d_in[1];
    float* out = (float*)d_out;

    cudaFuncSetAttribute(k_tconv<128, false>, cudaFuncAttributeMaxDynamicSharedMemorySize, SMEM_BYTES);
    cudaFuncSetAttribute(k_tconv<64, true>,   cudaFuncAttributeMaxDynamicSharedMemorySize, SMEM_BYTES);

    k_norm<<<NATOMS, 256>>>(d);
    k_prep<<<NATOMS, 256>>>();
    {
        int n = BATCH * T_LEN;
        k_init_out<<<(n + 255) / 256, 256>>>(x, out);
    }
    k_tconv<128, false><<<dim3(T_LEN / 128, NATOMS / TM, BATCH), 256, SMEM_BYTES>>>(x);
    k_bmax_init<<<dim3(NBLK, NATOMS, BATCH), 256>>>();

    for (int it = 0; it < N_ITER; it++) {
        k_select_apply<<<BATCH, 512>>>(out);
        if (it < N_ITER - 1) {     // last iteration's fm update is never read
            k_tconv<64, true><<<dim3(1024 / 64, NATOMS / TM, BATCH), 256, SMEM_BYTES>>>(x);
            k_refresh<<<dim3(2, NATOMS, BATCH), 256>>>();
        }
    }
}

// round 8
// speedup vs baseline: 1.1619x; 1.1619x over previous
#include <cuda_runtime.h>
#include <math.h>
#include <cstdint>

#define T_LEN   16384
#define NATOMS  512
#define ALEN    512
#define BATCH   8
#define NBLK    16
#define BLKSZ   1024
#define SIGL    1536
#define N_ITER  32
#define EPS_N   1e-8f

#define TM 128                 // atoms per CTA tile
#define KC 64                  // K chunk
#define NCHUNK (ALEN / KC)     // 8
#define APAD 68                // padded a-stride in smem
#define TNP 128                // t positions per tile
#define NI  (TNP / 32)
#define SWIN (TNP + ALEN)      // staged signal window
#define SSTR (SWIN + 8)
#define SMEM_BYTES ((4 * TM * APAD + 2 * SSTR) * 4)   // 144448 B
#define PCTAS 128              // persistent grid (co-resident, 1/SM)

// ---------------- device-global scratch ----------------
__device__ float g_dn[NATOMS * ALEN];
__device__ __align__(16) uint32_t g_dtf[2 * NATOMS * ALEN];   // tf32 big/small splits
__device__ float g_fm[(size_t)BATCH * NATOMS * T_LEN];        // 256 MB
__device__ float g_bmax[BATCH * NATOMS * NBLK];
__device__ int   g_barg[BATCH * NATOMS * NBLK];
__device__ float g_sig[BATCH * SIGL];
__device__ float g_selv[BATCH];
__device__ int   g_seln[BATCH];
__device__ int   g_selt[BATCH];
__device__ unsigned g_cnt = 0;     // grid-barrier arrive counter
__device__ unsigned g_gen = 0;     // grid-barrier generation

// ---------------- helpers ----------------
__device__ __forceinline__ uint32_t f2tf32(float v) {
    uint32_t r;
    asm("cvt.rna.tf32.f32 %0, %1;" : "=r"(r) : "f"(v));
    return r;
}
__device__ __forceinline__ void mma8(float* c, const uint32_t* a, const uint32_t* b) {
    asm volatile(
        "mma.sync.aligned.m16n8k8.row.col.f32.tf32.tf32.f32 "
        "{%0,%1,%2,%3}, {%4,%5,%6,%7}, {%8,%9}, {%0,%1,%2,%3};"
        : "+f"(c[0]), "+f"(c[1]), "+f"(c[2]), "+f"(c[3])
        : "r"(a[0]), "r"(a[1]), "r"(a[2]), "r"(a[3]), "r"(b[0]), "r"(b[1]));
}
#define CP_COMMIT() asm volatile("cp.async.commit_group;" ::: "memory")
#define CP_WAIT0()  asm volatile("cp.async.wait_group 0;" ::: "memory")
#define CP_WAIT1()  asm volatile("cp.async.wait_group 1;" ::: "memory")

__device__ __forceinline__ void stage_chunk_async(uint32_t* sAbuf, int n0, int a0, int tid) {
    #pragma unroll
    for (int e = tid; e < TM * 16; e += 256) {
        int kq = e & 15, n = e >> 4;
        size_t gi = (size_t)(n0 + n) * ALEN + a0 + kq * 4;
        uint32_t d0 = (uint32_t)__cvta_generic_to_shared(&sAbuf[n * APAD + kq * 4]);
        uint32_t d1 = (uint32_t)__cvta_generic_to_shared(&sAbuf[TM * APAD + n * APAD + kq * 4]);
        asm volatile("cp.async.cg.shared.global [%0], [%1], 16;" :: "r"(d0), "l"(&g_dtf[gi]) : "memory");
        asm volatile("cp.async.cg.shared.global [%0], [%1], 16;" :: "r"(d1), "l"(&g_dtf[NATOMS * ALEN + gi]) : "memory");
    }
}

// grid-wide barrier for the persistent kernel (all PCTAS co-resident)
__device__ __forceinline__ void gsync() {
    __syncthreads();
    if (threadIdx.x == 0) {
        unsigned gen = atomicAdd(&g_gen, 0u);     // read BEFORE arriving
        __threadfence();                          // publish this CTA's writes
        if (atomicInc(&g_cnt, PCTAS - 1) == PCTAS - 1) {
            atomicAdd(&g_gen, 1u);                // release
        } else {
            while (atomicAdd(&g_gen, 0u) == gen) __nanosleep(64);
        }
        __threadfence();                          // acquire
    }
    __syncthreads();
}

// ---------------- setup kernels ----------------
__global__ void k_norm(const float* __restrict__ d) {
    int n = blockIdx.x;
    int tid = threadIdx.x;
    __shared__ float red[256];
    float s = 0.f;
    for (int a = tid; a < ALEN; a += 256) { float v = d[n * ALEN + a]; s += v * v; }
    red[tid] = s; __syncthreads();
    for (int st = 128; st > 0; st >>= 1) {
        if (tid < st) red[tid] += red[tid + st];
        __syncthreads();
    }
    float inv = 1.0f / (sqrtf(red[0]) + EPS_N);
    for (int a = tid; a < ALEN; a += 256) g_dn[n * ALEN + a] = d[n * ALEN + a] * inv;
}

__global__ void k_prep() {
    int n = blockIdx.x;
    for (int a = threadIdx.x; a < ALEN; a += 256) {
        float v = g_dn[n * ALEN + a];
        uint32_t big = f2tf32(v);
        float rem = v - __uint_as_float(big);
        g_dtf[n * ALEN + a] = big;
        g_dtf[NATOMS * ALEN + n * ALEN + a] = f2tf32(rem);
    }
}

__global__ void k_init_out(const float* __restrict__ x, float* __restrict__ out) {
    int i = blockIdx.x * blockDim.x + threadIdx.x;
    int n = BATCH * T_LEN;
    if (i < n) { out[i] = x[i]; out[n + i] = 0.f; }
}

// ---------------- full correlation (3xTF32, cp.async double-buffered) ----------------
__global__ __launch_bounds__(256, 1) void k_conv_full(const float* __restrict__ x) {
    extern __shared__ __align__(16) uint32_t sm[];
    uint32_t* sA = sm;
    uint32_t* sS = sm + 4 * TM * APAD;

    const int b  = blockIdx.z;
    const int n0 = blockIdx.y * TM;
    const int t0 = blockIdx.x * TNP;
    const int tid = threadIdx.x;
    const int lane = tid & 31;
    const int wm = (tid >> 5) & 1;
    const int wn = tid >> 6;
    const int g = lane >> 2;
    const int tig = lane & 3;

    const float* sig = x + (size_t)b * T_LEN;

    stage_chunk_async(sA, n0, 0, tid);
    CP_COMMIT();

    for (int i = tid; i < SWIN; i += 256) {
        int gi = t0 + i;
        float v = (gi < T_LEN) ? sig[gi] : 0.f;
        uint32_t big = f2tf32(v);
        float rem = v - __uint_as_float(big);
        sS[i] = big;
        sS[SSTR + i] = f2tf32(rem);
    }

    float acc[4][NI][4];
    #pragma unroll
    for (int mi = 0; mi < 4; mi++)
        #pragma unroll
        for (int ni = 0; ni < NI; ni++)
            #pragma unroll
            for (int q = 0; q < 4; q++) acc[mi][ni][q] = 0.f;

    for (int i = 0; i < NCHUNK; i++) {
        if (i + 1 < NCHUNK) {
            stage_chunk_async(sA + ((i + 1) & 1) * 2 * TM * APAD, n0, (i + 1) * KC, tid);
            CP_COMMIT();
            CP_WAIT1();
        } else {
            CP_WAIT0();
        }
        __syncthreads();
        const uint32_t* base = sA + (i & 1) * 2 * TM * APAD;
        const int a0 = i * KC;

        #pragma unroll
        for (int kk = 0; kk < KC / 8; kk++) {
            const int col = kk * 8 + tig;
            uint32_t Ab[4][4], As[4][4], Bb[NI][2], Bs[NI][2];
            #pragma unroll
            for (int mi = 0; mi < 4; mi++) {
                int rm = wm * 64 + mi * 16 + g;
                const uint32_t* p = &base[rm * APAD + col];
                Ab[mi][0] = p[0];
                Ab[mi][1] = p[8 * APAD];
                Ab[mi][2] = p[4];
                Ab[mi][3] = p[8 * APAD + 4];
                const uint32_t* q = p + TM * APAD;
                As[mi][0] = q[0];
                As[mi][1] = q[8 * APAD];
                As[mi][2] = q[4];
                As[mi][3] = q[8 * APAD + 4];
            }
            #pragma unroll
            for (int ni = 0; ni < NI; ni++) {
                int idx = wn * (TNP / 4) + ni * 8 + g + a0 + col;
                Bb[ni][0] = sS[idx];
                Bb[ni][1] = sS[idx + 4];
                Bs[ni][0] = sS[SSTR + idx];
                Bs[ni][1] = sS[SSTR + idx + 4];
            }
            #pragma unroll
            for (int mi = 0; mi < 4; mi++)
                #pragma unroll
                for (int ni = 0; ni < NI; ni++) {
                    mma8(acc[mi][ni], As[mi], Bb[ni]);
                    mma8(acc[mi][ni], Ab[mi], Bs[ni]);
                    mma8(acc[mi][ni], Ab[mi], Bb[ni]);
                }
        }
        __syncthreads();
    }

    #pragma unroll
    for (int mi = 0; mi < 4; mi++) {
        int n1 = n0 + wm * 64 + mi * 16 + g;
        float* row1 = g_fm + ((size_t)(b * NATOMS + n1)) * T_LEN;
        float* row2 = row1 + 8 * (size_t)T_LEN;
        #pragma unroll
        for (int ni = 0; ni < NI; ni++) {
            int tc = t0 + wn * (TNP / 4) + ni * 8 + tig * 2;
            *(float2*)(row1 + tc) = make_float2(acc[mi][ni][0], acc[mi][ni][1]);
            *(float2*)(row2 + tc) = make_float2(acc[mi][ni][2], acc[mi][ni][3]);
        }
    }
}

// ---------------- initial block-max ----------------
__global__ __launch_bounds__(256) void k_bmax_init() {
    int b = blockIdx.z, n = blockIdx.y, bl = blockIdx.x;
    const float* row = &g_fm[((size_t)(b * NATOMS + n)) * T_LEN + bl * BLKSZ];
    int tid = threadIdx.x;
    float4 v = *reinterpret_cast<const float4*>(&row[tid * 4]);
    float bv = v.x; int bt = tid * 4;
    if (v.y > bv) { bv = v.y; bt = tid * 4 + 1; }
    if (v.z > bv) { bv = v.z; bt = tid * 4 + 2; }
    if (v.w > bv) { bv = v.w; bt = tid * 4 + 3; }
    __shared__ float sv[256];
    __shared__ int   st[256];
    sv[tid] = bv; st[tid] = bt;
    __syncthreads();
    for (int s = 128; s > 0; s >>= 1) {
        if (tid < s) {
            if (sv[tid + s] > sv[tid] || (sv[tid + s] == sv[tid] && st[tid + s] < st[tid])) {
                sv[tid] = sv[tid + s]; st[tid] = st[tid + s];
            }
        }
        __syncthreads();
    }
    if (tid == 0) {
        int idx = (b * NATOMS + n) * NBLK + bl;
        g_bmax[idx] = sv[0];
        g_barg[idx] = bl * BLKSZ + st[0];
    }
}

// ---------------- persistent-loop device phases ----------------
__device__ void select_apply_dev(int b, float* __restrict__ out) {
    __shared__ float sv[256];
    __shared__ int   sf[256];
    int tid = threadIdx.x;
    float bv = -3.402823466e38f;
    int   bf = 0x7FFFFFFF;
    const float* bm = &g_bmax[b * NATOMS * NBLK];
    const int*   ba = &g_barg[b * NATOMS * NBLK];
    for (int idx = tid; idx < NATOMS * NBLK; idx += 256) {
        float v = bm[idx];
        int flat = (idx >> 4) * T_LEN + ba[idx];
        if (v > bv || (v == bv && flat < bf)) { bv = v; bf = flat; }
    }
    sv[tid] = bv; sf[tid] = bf;
    __syncthreads();
    for (int s = 128; s > 0; s >>= 1) {
        if (tid < s) {
            if (sv[tid + s] > sv[tid] || (sv[tid + s] == sv[tid] && sf[tid + s] < sf[tid])) {
                sv[tid] = sv[tid + s]; sf[tid] = sf[tid + s];
            }
        }
        __syncthreads();
    }
    float v = sv[0];
    int n = sf[0] >> 14;
    int t = sf[0] & (T_LEN - 1);
    if (tid == 0) { g_selv[b] = v; g_seln[b] = n; g_selt[b] = t; }
    int end = min(t + ALEN, T_LEN - 1);   // ref clips: position T-1 never written
    int L = end - t;
    float* res = out + (size_t)b * T_LEN;
    float* rec = out + (size_t)(BATCH + b) * T_LEN;
    for (int u = tid; u < L; u += 256) {
        float w = v * g_dn[n * ALEN + u];
        res[t + u] -= w;
        rec[t + u] += w;
    }
    for (int u = tid; u < SIGL; u += 256) {
        int j = u - (ALEN - 1);
        g_sig[b * SIGL + u] = (j >= 0 && j < L) ? v * g_dn[n * ALEN + j] : 0.f;
    }
}

__device__ void delta_tile(uint32_t* __restrict__ sm, int b, int n0, int t0) {
    uint32_t* sA = sm;
    uint32_t* sS = sm + 4 * TM * APAD;
    const int tid = threadIdx.x;
    const int lane = tid & 31;
    const int wm = (tid >> 5) & 1;
    const int wn = tid >> 6;
    const int g = lane >> 2;
    const int tig = lane & 3;

    int tsel = g_selt[b];
    int off = tsel - (ALEN - 1);
    if (off + t0 >= T_LEN || off + t0 + TNP - 1 < 0) return;
    int L = min(tsel + ALEN, T_LEN - 1) - tsel;
    if (L <= 0) return;
    unsigned cmask = 0;
    for (int c = 0; c < NCHUNK; c++) {
        int lo = t0 + c * KC;
        int hi = lo + (TNP - 1) + (KC - 1);
        if (lo < (ALEN - 1) + L && hi >= (ALEN - 1)) cmask |= 1u << c;
    }
    if (!cmask) return;

    const float* sig = g_sig + b * SIGL;

    int clist[NCHUNK];
    int ncl = 0;
    for (int c = 0; c < NCHUNK; c++)
        if ((cmask >> c) & 1) clist[ncl++] = c;

    stage_chunk_async(sA, n0, clist[0] * KC, tid);
    CP_COMMIT();

    for (int i = tid; i < SWIN; i += 256) {
        int gi = t0 + i;
        float v = (gi < SIGL) ? sig[gi] : 0.f;
        uint32_t big = f2tf32(v);
        float rem = v - __uint_as_float(big);
        sS[i] = big;
        sS[SSTR + i] = f2tf32(rem);
    }

    float acc[4][NI][4];
    #pragma unroll
    for (int mi = 0; mi < 4; mi++)
        #pragma unroll
        for (int ni = 0; ni < NI; ni++)
            #pragma unroll
            for (int q = 0; q < 4; q++) acc[mi][ni][q] = 0.f;

    for (int i = 0; i < ncl; i++) {
        if (i + 1 < ncl) {
            stage_chunk_async(sA + ((i + 1) & 1) * 2 * TM * APAD, n0, clist[i + 1] * KC, tid);
            CP_COMMIT();
            CP_WAIT1();
        } else {
            CP_WAIT0();
        }
        __syncthreads();
        const uint32_t* base = sA + (i & 1) * 2 * TM * APAD;
        const int a0 = clist[i] * KC;

        #pragma unroll
        for (int kk = 0; kk < KC / 8; kk++) {
            const int col = kk * 8 + tig;
            uint32_t Ab[4][4], As[4][4], Bb[NI][2], Bs[NI][2];
            #pragma unroll
            for (int mi = 0; mi < 4; mi++) {
                int rm = wm * 64 + mi * 16 + g;
                const uint32_t* p = &base[rm * APAD + col];
                Ab[mi][0] = p[0];
                Ab[mi][1] = p[8 * APAD];
                Ab[mi][2] = p[4];
                Ab[mi][3] = p[8 * APAD + 4];
                const uint32_t* q = p + TM * APAD;
                As[mi][0] = q[0];
                As[mi][1] = q[8 * APAD];
                As[mi][2] = q[4];
                As[mi][3] = q[8 * APAD + 4];
            }
            #pragma unroll
            for (int ni = 0; ni < NI; ni++) {
                int idx = wn * (TNP / 4) + ni * 8 + g + a0 + col;
                Bb[ni][0] = sS[idx];
                Bb[ni][1] = sS[idx + 4];
                Bs[ni][0] = sS[SSTR + idx];
                Bs[ni][1] = sS[SSTR + idx + 4];
            }
            #pragma unroll
            for (int mi = 0; mi < 4; mi++)
                #pragma unroll
                for (int ni = 0; ni < NI; ni++) {
                    mma8(acc[mi][ni], As[mi], Bb[ni]);
                    mma8(acc[mi][ni], Ab[mi], Bs[ni]);
                    mma8(acc[mi][ni], Ab[mi], Bb[ni]);
                }
        }
        __syncthreads();
    }

    #pragma unroll
    for (int mi = 0; mi < 4; mi++) {
        int n1 = n0 + wm * 64 + mi * 16 + g;
        float* row1 = g_fm + ((size_t)(b * NATOMS + n1)) * T_LEN;
        float* row2 = row1 + 8 * (size_t)T_LEN;
        #pragma unroll
        for (int ni = 0; ni < NI; ni++) {
            int tc = t0 + wn * (TNP / 4) + ni * 8 + tig * 2;
            int t = off + tc;
            if (t >= 0 && t < T_LEN)         row1[t]     -= acc[mi][ni][0];
            if (t + 1 >= 0 && t + 1 < T_LEN) row1[t + 1] -= acc[mi][ni][1];
            if (t >= 0 && t < T_LEN)         row2[t]     -= acc[mi][ni][2];
            if (t + 1 >= 0 && t + 1 < T_LEN) row2[t + 1] -= acc[mi][ni][3];
        }
    }
}

__device__ void refresh_dev() {
    int wgid = blockIdx.x * 8 + (threadIdx.x >> 5);
    int lane = threadIdx.x & 31;
    for (int u = wgid; u < BATCH * NATOMS * 2; u += PCTAS * 8) {
        int b = u >> 10;                       // NATOMS*2 = 1024
        int n = (u >> 1) & (NATOMS - 1);
        int which = u & 1;
        int t = g_selt[b];
        int lo = max(0, t - (ALEN - 1));
        int hi = min(T_LEN - 1, t + (ALEN - 1));
        int bl0 = lo >> 10, bl1 = hi >> 10;
        if (which == 1 && bl1 == bl0) continue;
        int bl = which ? bl1 : bl0;
        const float* row = &g_fm[((size_t)(b * NATOMS + n)) * T_LEN + bl * BLKSZ];
        float bv = -3.402823466e38f;
        int bt = 0x7FFFFFFF;
        #pragma unroll
        for (int i = 0; i < 8; i++) {
            int base = (i * 32 + lane) * 4;
            float4 v = *(const float4*)&row[base];
            if (v.x > bv) { bv = v.x; bt = base; }
            if (v.y > bv) { bv = v.y; bt = base + 1; }
            if (v.z > bv) { bv = v.z; bt = base + 2; }
            if (v.w > bv) { bv = v.w; bt = base + 3; }
        }
        #pragma unroll
        for (int o = 16; o > 0; o >>= 1) {
            float ov = __shfl_down_sync(0xFFFFFFFFu, bv, o);
            int   ot = __shfl_down_sync(0xFFFFFFFFu, bt, o);
            if (ov > bv || (ov == bv && ot < bt)) { bv = ov; bt = ot; }
        }
        if (lane == 0) {
            int idx = (b * NATOMS + n) * NBLK + bl;
            g_bmax[idx] = bv;
            g_barg[idx] = bl * BLKSZ + bt;
        }
    }
}

// ---------------- the persistent loop kernel ----------------
__global__ __launch_bounds__(256, 1) void k_loop(float* __restrict__ out) {
    extern __shared__ __align__(16) uint32_t sm[];
    for (int it = 0; it < N_ITER; it++) {
        // Phase A: select + apply (one CTA per batch)
        if (blockIdx.x < BATCH) select_apply_dev(blockIdx.x, out);
        if (it == N_ITER - 1) return;          // last iteration: fm update never read
        gsync();
        // Phase B: delta correlation, 256 tiles over PCTAS CTAs
        for (int tile = blockIdx.x; tile < 256; tile += PCTAS) {
            int b = tile >> 5;
            int r = tile & 31;
            delta_tile(sm, b, (r >> 3) * TM, (r & 7) * TNP);
        }
        gsync();
        // Phase C: refresh block maxima (warp per scan unit)
        refresh_dev();
        gsync();
    }
}

// ---------------- launch ----------------
extern "C" void kernel_launch(void* const* d_in, const int* in_sizes, int n_in,
                              void* d_out, int out_size) {
    const float* x = (const float*)d_in[0];
    const float* d = (const float*)d_in[1];
    float* out = (float*)d_out;

    cudaFuncSetAttribute(k_conv_full, cudaFuncAttributeMaxDynamicSharedMemorySize, SMEM_BYTES);
    cudaFuncSetAttribute(k_loop,      cudaFuncAttributeMaxDynamicSharedMemorySize, SMEM_BYTES);

    k_norm<<<NATOMS, 256>>>(d);
    k_prep<<<NATOMS, 256>>>();
    {
        int n = BATCH * T_LEN;
        k_init_out<<<(n + 255) / 256, 256>>>(x, out);
    }
    k_conv_full<<<dim3(T_LEN / TNP, NATOMS / TM, BATCH), 256, SMEM_BYTES>>>(x);
    k_bmax_init<<<dim3(NBLK, NATOMS, BATCH), 256>>>();
    k_loop<<<PCTAS, 256, SMEM_BYTES>>>(out);
}

// round 9
// speedup vs baseline: 1.7104x; 1.4721x over previous
#include <cuda_runtime.h>
#include <math.h>
#include <cstdint>

#define T_LEN   16384
#define NATOMS  512
#define ALEN    512
#define BATCH   8
#define NBLK    16
#define BLKSZ   1024
#define SIGL    1536
#define N_ITER  32
#define EPS_N   1e-8f

// full-conv tiling
#define TM 128
#define KC 64
#define NCHUNK (ALEN / KC)
#define APAD 68
#define TNP 128
#define NI  (TNP / 32)
#define SWIN (TNP + ALEN)
#define SSTR (SWIN + 8)
// loop kernel: resident dict slice
#define KSTR 516               // padded K stride (bank-conflict-free A frags)
#define SSL  1544              // padded signal split stride
#define SMEM_BYTES 144448      // max(conv, loop) — both 36112 u32
#define PCTAS 128
#define GRPSZ 16

// ---------------- device-global scratch ----------------
__device__ float g_dn[NATOMS * ALEN];
__device__ __align__(16) uint32_t g_dtf[2 * NATOMS * ALEN];
__device__ float g_fm[(size_t)BATCH * NATOMS * T_LEN];        // 256 MB
__device__ float g_bmax[BATCH * NATOMS * NBLK];
__device__ int   g_barg[BATCH * NATOMS * NBLK];
__device__ float g_sig[BATCH * SIGL];
__device__ float g_selv[BATCH];
__device__ int   g_seln[BATCH];
__device__ int   g_selt[BATCH];
__device__ unsigned g_cnt8[BATCH] = {0};
__device__ unsigned g_gen8[BATCH] = {0};

// ---------------- helpers ----------------
__device__ __forceinline__ uint32_t f2tf32(float v) {
    uint32_t r;
    asm("cvt.rna.tf32.f32 %0, %1;" : "=r"(r) : "f"(v));
    return r;
}
__device__ __forceinline__ void mma8(float* c, const uint32_t* a, const uint32_t* b) {
    asm volatile(
        "mma.sync.aligned.m16n8k8.row.col.f32.tf32.tf32.f32 "
        "{%0,%1,%2,%3}, {%4,%5,%6,%7}, {%8,%9}, {%0,%1,%2,%3};"
        : "+f"(c[0]), "+f"(c[1]), "+f"(c[2]), "+f"(c[3])
        : "r"(a[0]), "r"(a[1]), "r"(a[2]), "r"(a[3]), "r"(b[0]), "r"(b[1]));
}
#define CP_COMMIT() asm volatile("cp.async.commit_group;" ::: "memory")
#define CP_WAIT0()  asm volatile("cp.async.wait_group 0;" ::: "memory")
#define CP_WAIT1()  asm volatile("cp.async.wait_group 1;" ::: "memory")

__device__ __forceinline__ void stage_chunk_async(uint32_t* sAbuf, int n0, int a0, int tid) {
    #pragma unroll
    for (int e = tid; e < TM * 16; e += 256) {
        int kq = e & 15, n = e >> 4;
        size_t gi = (size_t)(n0 + n) * ALEN + a0 + kq * 4;
        uint32_t d0 = (uint32_t)__cvta_generic_to_shared(&sAbuf[n * APAD + kq * 4]);
        uint32_t d1 = (uint32_t)__cvta_generic_to_shared(&sAbuf[TM * APAD + n * APAD + kq * 4]);
        asm volatile("cp.async.cg.shared.global [%0], [%1], 16;" :: "r"(d0), "l"(&g_dtf[gi]) : "memory");
        asm volatile("cp.async.cg.shared.global [%0], [%1], 16;" :: "r"(d1), "l"(&g_dtf[NATOMS * ALEN + gi]) : "memory");
    }
}

// group-local barrier (GRPSZ co-resident CTAs of one batch)
__device__ __forceinline__ void gsync_grp(int grp) {
    __syncthreads();
    if (threadIdx.x == 0) {
        unsigned gen = atomicAdd(&g_gen8[grp], 0u);
        __threadfence();
        if (atomicInc(&g_cnt8[grp], GRPSZ - 1) == GRPSZ - 1) {
            atomicAdd(&g_gen8[grp], 1u);
        } else {
            while (atomicAdd(&g_gen8[grp], 0u) == gen) __nanosleep(32);
        }
        __threadfence();
    }
    __syncthreads();
}

// ---------------- setup kernels ----------------
__global__ void k_norm(const float* __restrict__ d) {
    int n = blockIdx.x;
    int tid = threadIdx.x;
    __shared__ float red[256];
    float s = 0.f;
    for (int a = tid; a < ALEN; a += 256) { float v = d[n * ALEN + a]; s += v * v; }
    red[tid] = s; __syncthreads();
    for (int st = 128; st > 0; st >>= 1) {
        if (tid < st) red[tid] += red[tid + st];
        __syncthreads();
    }
    float inv = 1.0f / (sqrtf(red[0]) + EPS_N);
    for (int a = tid; a < ALEN; a += 256) g_dn[n * ALEN + a] = d[n * ALEN + a] * inv;
}

__global__ void k_prep() {
    int n = blockIdx.x;
    for (int a = threadIdx.x; a < ALEN; a += 256) {
        float v = g_dn[n * ALEN + a];
        uint32_t big = f2tf32(v);
        float rem = v - __uint_as_float(big);
        g_dtf[n * ALEN + a] = big;
        g_dtf[NATOMS * ALEN + n * ALEN + a] = f2tf32(rem);
    }
}

__global__ void k_init_out(const float* __restrict__ x, float* __restrict__ out) {
    int i = blockIdx.x * blockDim.x + threadIdx.x;
    int n = BATCH * T_LEN;
    if (i < n) { out[i] = x[i]; out[n + i] = 0.f; }
}

// ---------------- full correlation (3xTF32, cp.async double-buffered) ----------------
__global__ __launch_bounds__(256, 1) void k_conv_full(const float* __restrict__ x) {
    extern __shared__ __align__(16) uint32_t sm[];
    uint32_t* sA = sm;
    uint32_t* sS = sm + 4 * TM * APAD;

    const int b  = blockIdx.z;
    const int n0 = blockIdx.y * TM;
    const int t0 = blockIdx.x * TNP;
    const int tid = threadIdx.x;
    const int lane = tid & 31;
    const int wm = (tid >> 5) & 1;
    const int wn = tid >> 6;
    const int g = lane >> 2;
    const int tig = lane & 3;

    const float* sig = x + (size_t)b * T_LEN;

    stage_chunk_async(sA, n0, 0, tid);
    CP_COMMIT();

    for (int i = tid; i < SWIN; i += 256) {
        int gi = t0 + i;
        float v = (gi < T_LEN) ? sig[gi] : 0.f;
        uint32_t big = f2tf32(v);
        float rem = v - __uint_as_float(big);
        sS[i] = big;
        sS[SSTR + i] = f2tf32(rem);
    }

    float acc[4][NI][4];
    #pragma unroll
    for (int mi = 0; mi < 4; mi++)
        #pragma unroll
        for (int ni = 0; ni < NI; ni++)
            #pragma unroll
            for (int q = 0; q < 4; q++) acc[mi][ni][q] = 0.f;

    for (int i = 0; i < NCHUNK; i++) {
        if (i + 1 < NCHUNK) {
            stage_chunk_async(sA + ((i + 1) & 1) * 2 * TM * APAD, n0, (i + 1) * KC, tid);
            CP_COMMIT();
            CP_WAIT1();
        } else {
            CP_WAIT0();
        }
        __syncthreads();
        const uint32_t* base = sA + (i & 1) * 2 * TM * APAD;
        const int a0 = i * KC;

        #pragma unroll
        for (int kk = 0; kk < KC / 8; kk++) {
            const int col = kk * 8 + tig;
            uint32_t Ab[4][4], As[4][4], Bb[NI][2], Bs[NI][2];
            #pragma unroll
            for (int mi = 0; mi < 4; mi++) {
                int rm = wm * 64 + mi * 16 + g;
                const uint32_t* p = &base[rm * APAD + col];
                Ab[mi][0] = p[0];
                Ab[mi][1] = p[8 * APAD];
                Ab[mi][2] = p[4];
                Ab[mi][3] = p[8 * APAD + 4];
                const uint32_t* q = p + TM * APAD;
                As[mi][0] = q[0];
                As[mi][1] = q[8 * APAD];
                As[mi][2] = q[4];
                As[mi][3] = q[8 * APAD + 4];
            }
            #pragma unroll
            for (int ni = 0; ni < NI; ni++) {
                int idx = wn * (TNP / 4) + ni * 8 + g + a0 + col;
                Bb[ni][0] = sS[idx];
                Bb[ni][1] = sS[idx + 4];
                Bs[ni][0] = sS[SSTR + idx];
                Bs[ni][1] = sS[SSTR + idx + 4];
            }
            #pragma unroll
            for (int mi = 0; mi < 4; mi++)
                #pragma unroll
                for (int ni = 0; ni < NI; ni++) {
                    mma8(acc[mi][ni], As[mi], Bb[ni]);
                    mma8(acc[mi][ni], Ab[mi], Bs[ni]);
                    mma8(acc[mi][ni], Ab[mi], Bb[ni]);
                }
        }
        __syncthreads();
    }

    #pragma unroll
    for (int mi = 0; mi < 4; mi++) {
        int n1 = n0 + wm * 64 + mi * 16 + g;
        float* row1 = g_fm + ((size_t)(b * NATOMS + n1)) * T_LEN;
        float* row2 = row1 + 8 * (size_t)T_LEN;
        #pragma unroll
        for (int ni = 0; ni < NI; ni++) {
            int tc = t0 + wn * (TNP / 4) + ni * 8 + tig * 2;
            *(float2*)(row1 + tc) = make_float2(acc[mi][ni][0], acc[mi][ni][1]);
            *(float2*)(row2 + tc) = make_float2(acc[mi][ni][2], acc[mi][ni][3]);
        }
    }
}

// ---------------- initial block-max ----------------
__global__ __launch_bounds__(256) void k_bmax_init() {
    int b = blockIdx.z, n = blockIdx.y, bl = blockIdx.x;
    const float* row = &g_fm[((size_t)(b * NATOMS + n)) * T_LEN + bl * BLKSZ];
    int tid = threadIdx.x;
    float4 v = *reinterpret_cast<const float4*>(&row[tid * 4]);
    float bv = v.x; int bt = tid * 4;
    if (v.y > bv) { bv = v.y; bt = tid * 4 + 1; }
    if (v.z > bv) { bv = v.z; bt = tid * 4 + 2; }
    if (v.w > bv) { bv = v.w; bt = tid * 4 + 3; }
    __shared__ float sv[256];
    __shared__ int   st[256];
    sv[tid] = bv; st[tid] = bt;
    __syncthreads();
    for (int s = 128; s > 0; s >>= 1) {
        if (tid < s) {
            if (sv[tid + s] > sv[tid] || (sv[tid + s] == sv[tid] && st[tid + s] < st[tid])) {
                sv[tid] = sv[tid + s]; st[tid] = st[tid + s];
            }
        }
        __syncthreads();
    }
    if (tid == 0) {
        int idx = (b * NATOMS + n) * NBLK + bl;
        g_bmax[idx] = sv[0];
        g_barg[idx] = bl * BLKSZ + st[0];
    }
}

// ---------------- select + apply (device, one CTA) ----------------
__device__ void select_apply_dev(int b, float* __restrict__ out) {
    __shared__ float sv[256];
    __shared__ int   sf[256];
    int tid = threadIdx.x;
    float bv = -3.402823466e38f;
    int   bf = 0x7FFFFFFF;
    const float* bm = &g_bmax[b * NATOMS * NBLK];
    const int*   ba = &g_barg[b * NATOMS * NBLK];
    for (int idx = tid; idx < NATOMS * NBLK; idx += 256) {
        float v = bm[idx];
        int flat = (idx >> 4) * T_LEN + ba[idx];
        if (v > bv || (v == bv && flat < bf)) { bv = v; bf = flat; }
    }
    sv[tid] = bv; sf[tid] = bf;
    __syncthreads();
    for (int s = 128; s > 0; s >>= 1) {
        if (tid < s) {
            if (sv[tid + s] > sv[tid] || (sv[tid + s] == sv[tid] && sf[tid + s] < sf[tid])) {
                sv[tid] = sv[tid + s]; sf[tid] = sf[tid + s];
            }
        }
        __syncthreads();
    }
    float v = sv[0];
    int n = sf[0] >> 14;
    int t = sf[0] & (T_LEN - 1);
    if (tid == 0) { g_selv[b] = v; g_seln[b] = n; g_selt[b] = t; }
    int end = min(t + ALEN, T_LEN - 1);   // ref clips: position T-1 never written
    int L = end - t;
    float* res = out + (size_t)b * T_LEN;
    float* rec = out + (size_t)(BATCH + b) * T_LEN;
    for (int u = tid; u < L; u += 256) {
        float w = v * g_dn[n * ALEN + u];
        res[t + u] -= w;
        rec[t + u] += w;
    }
    for (int u = tid; u < SIGL; u += 256) {
        int j = u - (ALEN - 1);
        g_sig[b * SIGL + u] = (j >= 0 && j < L) ? v * g_dn[n * ALEN + j] : 0.f;
    }
}

// ---------------- persistent loop: dict slice resident in smem ----------------
// CTA = (batch grp, 32-atom slice mem). Dict staged ONCE; per iteration:
//   A) select+apply (member 0)   B) delta over full 1024-t window   C) refresh
__global__ __launch_bounds__(256, 1) void k_loop(float* __restrict__ out) {
    extern __shared__ __align__(16) uint32_t sm[];
    uint32_t* sA = sm;                    // [2 splits][32 n][KSTR]
    uint32_t* sS = sm + 2 * 32 * KSTR;    // [2 splits][SSL]

    const int grp = blockIdx.x >> 4;      // batch
    const int mem = blockIdx.x & 15;      // n-slice
    const int n0 = mem * 32;
    const int tid = threadIdx.x;
    const int wid = tid >> 5;
    const int lane = tid & 31;
    const int g = lane >> 2;
    const int tig = lane & 3;

    // stage dictionary slice once (2 splits x 32 rows x 512 K)
    for (int e = tid; e < 2 * 32 * 128; e += 256) {
        int sp = e >> 12;
        int r  = (e >> 7) & 31;
        int kq = e & 127;
        size_t gi = (size_t)sp * NATOMS * ALEN + (size_t)(n0 + r) * ALEN + kq * 4;
        uint32_t dst = (uint32_t)__cvta_generic_to_shared(&sA[sp * 32 * KSTR + r * KSTR + kq * 4]);
        asm volatile("cp.async.cg.shared.global [%0], [%1], 16;" :: "r"(dst), "l"(&g_dtf[gi]) : "memory");
    }
    CP_COMMIT(); CP_WAIT0();
    __syncthreads();

    for (int it = 0; it < N_ITER; it++) {
        // Phase A
        if (mem == 0) select_apply_dev(grp, out);
        if (it == N_ITER - 1) return;
        gsync_grp(grp);

        // Phase B: delta for fm[grp, n0..n0+31, toff..toff+1023]
        int tsel = g_selt[grp];
        int toff = tsel - (ALEN - 1);
        int L = min(tsel + ALEN, T_LEN - 1) - tsel;
        if (L > 0) {
            for (int i = tid; i < SIGL; i += 256) {
                float v = g_sig[grp * SIGL + i];
                uint32_t big = f2tf32(v);
                sS[i] = big;
                sS[SSL + i] = f2tf32(v - __uint_as_float(big));
            }
            __syncthreads();

            #pragma unroll
            for (int pass = 0; pass < 2; pass++) {
                int tw = pass * 512 + wid * 64;          // warp's local t base
                // k support: exists t in [tw, tw+63] with t+k in [511, 511+L)
                int klo = max(0, (ALEN - 1) - (tw + 63)) & ~7;
                int khi = min(ALEN, (ALEN - 1) + L - tw);
                khi = (khi + 7) & ~7;
                if (klo >= khi) continue;

                float acc[2][8][4];
                #pragma unroll
                for (int mi = 0; mi < 2; mi++)
                    #pragma unroll
                    for (int ni = 0; ni < 8; ni++)
                        #pragma unroll
                        for (int q = 0; q < 4; q++) acc[mi][ni][q] = 0.f;

                for (int k0 = klo; k0 < khi; k0 += 8) {
                    int col = k0 + tig;
                    uint32_t Ab[2][4], As[2][4], Bb[8][2], Bs[8][2];
                    #pragma unroll
                    for (int mi = 0; mi < 2; mi++) {
                        const uint32_t* p = &sA[(mi * 16 + g) * KSTR + col];
                        Ab[mi][0] = p[0];
                        Ab[mi][1] = p[8 * KSTR];
                        Ab[mi][2] = p[4];
                        Ab[mi][3] = p[8 * KSTR + 4];
                        const uint32_t* q = p + 32 * KSTR;
                        As[mi][0] = q[0];
                        As[mi][1] = q[8 * KSTR];
                        As[mi][2] = q[4];
                        As[mi][3] = q[8 * KSTR + 4];
                    }
                    #pragma unroll
                    for (int ni = 0; ni < 8; ni++) {
                        int idx = tw + ni * 8 + g + col;
                        Bb[ni][0] = sS[idx];
                        Bb[ni][1] = sS[idx + 4];
                        Bs[ni][0] = sS[SSL + idx];
                        Bs[ni][1] = sS[SSL + idx + 4];
                    }
                    #pragma unroll
                    for (int mi = 0; mi < 2; mi++)
                        #pragma unroll
                        for (int ni = 0; ni < 8; ni++) {
                            mma8(acc[mi][ni], As[mi], Bb[ni]);
                            mma8(acc[mi][ni], Ab[mi], Bs[ni]);
                            mma8(acc[mi][ni], Ab[mi], Bb[ni]);
                        }
                }

                #pragma unroll
                for (int mi = 0; mi < 2; mi++) {
                    int n1 = n0 + mi * 16 + g;
                    float* row1 = g_fm + ((size_t)(grp * NATOMS + n1)) * T_LEN;
                    float* row2 = row1 + 8 * (size_t)T_LEN;
                    #pragma unroll
                    for (int ni = 0; ni < 8; ni++) {
                        int t = toff + tw + ni * 8 + tig * 2;
                        if (t >= 0 && t < T_LEN)         row1[t]     -= acc[mi][ni][0];
                        if (t + 1 >= 0 && t + 1 < T_LEN) row1[t + 1] -= acc[mi][ni][1];
                        if (t >= 0 && t < T_LEN)         row2[t]     -= acc[mi][ni][2];
                        if (t + 1 >= 0 && t + 1 < T_LEN) row2[t + 1] -= acc[mi][ni][3];
                    }
                }
            }
        }
        gsync_grp(grp);

        // Phase C: refresh block maxima for this batch (warp per scan unit)
        {
            int wg = mem * 8 + wid;       // 0..127
            int t = g_selt[grp];
            int lo = max(0, t - (ALEN - 1));
            int hi = min(T_LEN - 1, t + (ALEN - 1));
            int bl0 = lo >> 10, bl1 = hi >> 10;
            for (int u = wg; u < NATOMS * 2; u += GRPSZ * 8) {
                int n = u >> 1;
                int which = u & 1;
                if (which == 1 && bl1 == bl0) continue;
                int bl = which ? bl1 : bl0;
                const float* row = &g_fm[((size_t)(grp * NATOMS + n)) * T_LEN + bl * BLKSZ];
                float bv = -3.402823466e38f;
                int bt = 0x7FFFFFFF;
                #pragma unroll
                for (int i = 0; i < 8; i++) {
                    int base = (i * 32 + lane) * 4;
                    float4 v = *(const float4*)&row[base];
                    if (v.x > bv) { bv = v.x; bt = base; }
                    if (v.y > bv) { bv = v.y; bt = base + 1; }
                    if (v.z > bv) { bv = v.z; bt = base + 2; }
                    if (v.w > bv) { bv = v.w; bt = base + 3; }
                }
                #pragma unroll
                for (int o = 16; o > 0; o >>= 1) {
                    float ov = __shfl_down_sync(0xFFFFFFFFu, bv, o);
                    int   ot = __shfl_down_sync(0xFFFFFFFFu, bt, o);
                    if (ov > bv || (ov == bv && ot < bt)) { bv = ov; bt = ot; }
                }
                if (lane == 0) {
                    int idx = (grp * NATOMS + n) * NBLK + bl;
                    g_bmax[idx] = bv;
                    g_barg[idx] = bl * BLKSZ + bt;
                }
            }
        }
        gsync_grp(grp);
    }
}

// ---------------- launch ----------------
extern "C" void kernel_launch(void* const* d_in, const int* in_sizes, int n_in,
                              void* d_out, int out_size) {
    const float* x = (const float*)d_in[0];
    const float* d = (const float*)d_in[1];
    float* out = (float*)d_out;

    cudaFuncSetAttribute(k_conv_full, cudaFuncAttributeMaxDynamicSharedMemorySize, SMEM_BYTES);
    cudaFuncSetAttribute(k_loop,      cudaFuncAttributeMaxDynamicSharedMemorySize, SMEM_BYTES);

    k_norm<<<NATOMS, 256>>>(d);
    k_prep<<<NATOMS, 256>>>();
    {
        int n = BATCH * T_LEN;
        k_init_out<<<(n + 255) / 256, 256>>>(x, out);
    }
    k_conv_full<<<dim3(T_LEN / TNP, NATOMS / TM, BATCH), 256, SMEM_BYTES>>>(x);
    k_bmax_init<<<dim3(NBLK, NATOMS, BATCH), 256>>>();
    k_loop<<<PCTAS, 256, SMEM_BYTES>>>(out);
}

// round 10
// speedup vs baseline: 1.8122x; 1.0596x over previous
#include <cuda_runtime.h>
#include <math.h>
#include <cstdint>

#define T_LEN   16384
#define NATOMS  512
#define ALEN    512
#define BATCH   8
#define NBLK    16
#define BLKSZ   1024
#define SIGL    1536
#define N_ITER  32
#define EPS_N   1e-8f

// full-conv tiling
#define TM 128
#define KC 64
#define NCHUNK (ALEN / KC)
#define APAD 68
#define TNP 128
#define NI  (TNP / 32)
#define SWIN (TNP + ALEN)
#define SSTR (SWIN + 8)
// loop kernel
#define KSTR 516
#define SSL  1544
#define SMEM_BYTES 144448
#define PCTAS 128
#define GRPSZ 16

// ---------------- device-global scratch ----------------
__device__ float g_dn[NATOMS * ALEN];
__device__ __align__(16) uint32_t g_dtf[2 * NATOMS * ALEN];
__device__ float g_fm[(size_t)BATCH * NATOMS * T_LEN];        // 256 MB
__device__ float g_bmax[BATCH * NATOMS * NBLK];
__device__ int   g_barg[BATCH * NATOMS * NBLK];
__device__ unsigned long long g_best[2][BATCH] = {{0}};
__device__ unsigned g_cnt8[BATCH] = {0};
__device__ unsigned g_gen8[BATCH] = {0};

// ---------------- helpers ----------------
__device__ __forceinline__ uint32_t f2tf32(float v) {
    uint32_t r;
    asm("cvt.rna.tf32.f32 %0, %1;" : "=r"(r) : "f"(v));
    return r;
}
__device__ __forceinline__ void mma8(float* c, const uint32_t* a, const uint32_t* b) {
    asm volatile(
        "mma.sync.aligned.m16n8k8.row.col.f32.tf32.tf32.f32 "
        "{%0,%1,%2,%3}, {%4,%5,%6,%7}, {%8,%9}, {%0,%1,%2,%3};"
        : "+f"(c[0]), "+f"(c[1]), "+f"(c[2]), "+f"(c[3])
        : "r"(a[0]), "r"(a[1]), "r"(a[2]), "r"(a[3]), "r"(b[0]), "r"(b[1]));
}
#define CP_COMMIT() asm volatile("cp.async.commit_group;" ::: "memory")
#define CP_WAIT0()  asm volatile("cp.async.wait_group 0;" ::: "memory")
#define CP_WAIT1()  asm volatile("cp.async.wait_group 1;" ::: "memory")

// monotonic float->uint key; low word = 0xFFFFFFFF - flat (first-on-tie via max)
__device__ __forceinline__ unsigned long long pack_key(float v, unsigned flat) {
    unsigned u = __float_as_uint(v);
    unsigned key = (u & 0x80000000u) ? ~u : (u | 0x80000000u);
    return ((unsigned long long)key << 32) | (0xFFFFFFFFu - flat);
}

__device__ __forceinline__ void stage_chunk_async(uint32_t* sAbuf, int n0, int a0, int tid) {
    #pragma unroll
    for (int e = tid; e < TM * 16; e += 256) {
        int kq = e & 15, n = e >> 4;
        size_t gi = (size_t)(n0 + n) * ALEN + a0 + kq * 4;
        uint32_t d0 = (uint32_t)__cvta_generic_to_shared(&sAbuf[n * APAD + kq * 4]);
        uint32_t d1 = (uint32_t)__cvta_generic_to_shared(&sAbuf[TM * APAD + n * APAD + kq * 4]);
        asm volatile("cp.async.cg.shared.global [%0], [%1], 16;" :: "r"(d0), "l"(&g_dtf[gi]) : "memory");
        asm volatile("cp.async.cg.shared.global [%0], [%1], 16;" :: "r"(d1), "l"(&g_dtf[NATOMS * ALEN + gi]) : "memory");
    }
}

// group-local barrier (GRPSZ co-resident CTAs of one batch)
__device__ __forceinline__ void gsync_grp(int grp) {
    __syncthreads();
    if (threadIdx.x == 0) {
        unsigned gen = atomicAdd(&g_gen8[grp], 0u);
        __threadfence();
        if (atomicInc(&g_cnt8[grp], GRPSZ - 1) == GRPSZ - 1) {
            atomicAdd(&g_gen8[grp], 1u);
        } else {
            while (atomicAdd(&g_gen8[grp], 0u) == gen) __nanosleep(32);
        }
        __threadfence();
    }
    __syncthreads();
}

// ---------------- setup kernels ----------------
__global__ void k_norm(const float* __restrict__ d) {
    int n = blockIdx.x;
    int tid = threadIdx.x;
    __shared__ float red[256];
    float s = 0.f;
    for (int a = tid; a < ALEN; a += 256) { float v = d[n * ALEN + a]; s += v * v; }
    red[tid] = s; __syncthreads();
    for (int st = 128; st > 0; st >>= 1) {
        if (tid < st) red[tid] += red[tid + st];
        __syncthreads();
    }
    float inv = 1.0f / (sqrtf(red[0]) + EPS_N);
    for (int a = tid; a < ALEN; a += 256) g_dn[n * ALEN + a] = d[n * ALEN + a] * inv;
}

__global__ void k_prep() {
    int n = blockIdx.x;
    for (int a = threadIdx.x; a < ALEN; a += 256) {
        float v = g_dn[n * ALEN + a];
        uint32_t big = f2tf32(v);
        float rem = v - __uint_as_float(big);
        g_dtf[n * ALEN + a] = big;
        g_dtf[NATOMS * ALEN + n * ALEN + a] = f2tf32(rem);
    }
}

__global__ void k_init_out(const float* __restrict__ x, float* __restrict__ out) {
    int i = blockIdx.x * blockDim.x + threadIdx.x;
    int n = BATCH * T_LEN;
    if (i < n) { out[i] = x[i]; out[n + i] = 0.f; }
}

// ---------------- full correlation (3xTF32, cp.async double-buffered) ----------------
__global__ __launch_bounds__(256, 1) void k_conv_full(const float* __restrict__ x) {
    extern __shared__ __align__(16) uint32_t sm[];
    uint32_t* sA = sm;
    uint32_t* sS = sm + 4 * TM * APAD;

    const int b  = blockIdx.z;
    const int n0 = blockIdx.y * TM;
    const int t0 = blockIdx.x * TNP;
    const int tid = threadIdx.x;
    const int lane = tid & 31;
    const int wm = (tid >> 5) & 1;
    const int wn = tid >> 6;
    const int g = lane >> 2;
    const int tig = lane & 3;

    const float* sig = x + (size_t)b * T_LEN;

    stage_chunk_async(sA, n0, 0, tid);
    CP_COMMIT();

    for (int i = tid; i < SWIN; i += 256) {
        int gi = t0 + i;
        float v = (gi < T_LEN) ? sig[gi] : 0.f;
        uint32_t big = f2tf32(v);
        float rem = v - __uint_as_float(big);
        sS[i] = big;
        sS[SSTR + i] = f2tf32(rem);
    }

    float acc[4][NI][4];
    #pragma unroll
    for (int mi = 0; mi < 4; mi++)
        #pragma unroll
        for (int ni = 0; ni < NI; ni++)
            #pragma unroll
            for (int q = 0; q < 4; q++) acc[mi][ni][q] = 0.f;

    for (int i = 0; i < NCHUNK; i++) {
        if (i + 1 < NCHUNK) {
            stage_chunk_async(sA + ((i + 1) & 1) * 2 * TM * APAD, n0, (i + 1) * KC, tid);
            CP_COMMIT();
            CP_WAIT1();
        } else {
            CP_WAIT0();
        }
        __syncthreads();
        const uint32_t* base = sA + (i & 1) * 2 * TM * APAD;
        const int a0 = i * KC;

        #pragma unroll
        for (int kk = 0; kk < KC / 8; kk++) {
            const int col = kk * 8 + tig;
            uint32_t Ab[4][4], As[4][4], Bb[NI][2], Bs[NI][2];
            #pragma unroll
            for (int mi = 0; mi < 4; mi++) {
                int rm = wm * 64 + mi * 16 + g;
                const uint32_t* p = &base[rm * APAD + col];
                Ab[mi][0] = p[0];
                Ab[mi][1] = p[8 * APAD];
                Ab[mi][2] = p[4];
                Ab[mi][3] = p[8 * APAD + 4];
                const uint32_t* q = p + TM * APAD;
                As[mi][0] = q[0];
                As[mi][1] = q[8 * APAD];
                As[mi][2] = q[4];
                As[mi][3] = q[8 * APAD + 4];
            }
            #pragma unroll
            for (int ni = 0; ni < NI; ni++) {
                int idx = wn * (TNP / 4) + ni * 8 + g + a0 + col;
                Bb[ni][0] = sS[idx];
                Bb[ni][1] = sS[idx + 4];
                Bs[ni][0] = sS[SSTR + idx];
                Bs[ni][1] = sS[SSTR + idx + 4];
            }
            #pragma unroll
            for (int mi = 0; mi < 4; mi++)
                #pragma unroll
                for (int ni = 0; ni < NI; ni++) {
                    mma8(acc[mi][ni], As[mi], Bb[ni]);
                    mma8(acc[mi][ni], Ab[mi], Bs[ni]);
                    mma8(acc[mi][ni], Ab[mi], Bb[ni]);
                }
        }
        __syncthreads();
    }

    #pragma unroll
    for (int mi = 0; mi < 4; mi++) {
        int n1 = n0 + wm * 64 + mi * 16 + g;
        float* row1 = g_fm + ((size_t)(b * NATOMS + n1)) * T_LEN;
        float* row2 = row1 + 8 * (size_t)T_LEN;
        #pragma unroll
        for (int ni = 0; ni < NI; ni++) {
            int tc = t0 + wn * (TNP / 4) + ni * 8 + tig * 2;
            *(float2*)(row1 + tc) = make_float2(acc[mi][ni][0], acc[mi][ni][1]);
            *(float2*)(row2 + tc) = make_float2(acc[mi][ni][2], acc[mi][ni][3]);
        }
    }
}

// ---------------- initial block-max ----------------
__global__ __launch_bounds__(256) void k_bmax_init() {
    int b = blockIdx.z, n = blockIdx.y, bl = blockIdx.x;
    const float* row = &g_fm[((size_t)(b * NATOMS + n)) * T_LEN + bl * BLKSZ];
    int tid = threadIdx.x;
    float4 v = *reinterpret_cast<const float4*>(&row[tid * 4]);
    float bv = v.x; int bt = tid * 4;
    if (v.y > bv) { bv = v.y; bt = tid * 4 + 1; }
    if (v.z > bv) { bv = v.z; bt = tid * 4 + 2; }
    if (v.w > bv) { bv = v.w; bt = tid * 4 + 3; }
    __shared__ float sv[256];
    __shared__ int   st[256];
    sv[tid] = bv; st[tid] = bt;
    __syncthreads();
    for (int s = 128; s > 0; s >>= 1) {
        if (tid < s) {
            if (sv[tid + s] > sv[tid] || (sv[tid + s] == sv[tid] && st[tid + s] < st[tid])) {
                sv[tid] = sv[tid + s]; st[tid] = st[tid + s];
            }
        }
        __syncthreads();
    }
    if (tid == 0) {
        int idx = (b * NATOMS + n) * NBLK + bl;
        g_bmax[idx] = sv[0];
        g_barg[idx] = bl * BLKSZ + st[0];
    }
}

// ---------------- persistent loop: 2 barriers/iter, fully distributed ----------------
__global__ __launch_bounds__(256, 1) void k_loop(float* __restrict__ out) {
    extern __shared__ __align__(16) uint32_t sm[];
    uint32_t* sA = sm;                    // [2 splits][32 n][KSTR]
    uint32_t* sS = sm + 2 * 32 * KSTR;    // [2 splits][SSL]
    __shared__ unsigned long long s_part[8];
    __shared__ unsigned long long s_best;

    const int grp = blockIdx.x >> 4;
    const int mem = blockIdx.x & 15;
    const int n0 = mem * 32;
    const int tid = threadIdx.x;
    const int wid = tid >> 5;
    const int lane = tid & 31;
    const int g = lane >> 2;
    const int tig = lane & 3;

    // stage dictionary slice once
    for (int e = tid; e < 2 * 32 * 128; e += 256) {
        int sp = e >> 12;
        int r  = (e >> 7) & 31;
        int kq = e & 127;
        size_t gi = (size_t)sp * NATOMS * ALEN + (size_t)(n0 + r) * ALEN + kq * 4;
        uint32_t dst = (uint32_t)__cvta_generic_to_shared(&sA[sp * 32 * KSTR + r * KSTR + kq * 4]);
        asm volatile("cp.async.cg.shared.global [%0], [%1], 16;" :: "r"(dst), "l"(&g_dtf[gi]) : "memory");
    }
    CP_COMMIT(); CP_WAIT0();
    __syncthreads();

    for (int it = 0; it < N_ITER; it++) {
        // ---- A-scan: this CTA's 512 (bmax,barg) entries -> one atomicMax ----
        {
            int base = (grp * NATOMS + n0) * NBLK;
            unsigned long long best = 0ull;
            #pragma unroll
            for (int r = 0; r < 2; r++) {
                int e = tid + r * 256;
                float v = g_bmax[base + e];
                unsigned flat = (unsigned)((n0 + (e >> 4)) * T_LEN + g_barg[base + e]);
                unsigned long long k = pack_key(v, flat);
                if (k > best) best = k;
            }
            #pragma unroll
            for (int o = 16; o > 0; o >>= 1) {
                unsigned long long ok = __shfl_down_sync(0xFFFFFFFFu, best, o);
                if (ok > best) best = ok;
            }
            if (lane == 0) s_part[wid] = best;
            __syncthreads();
            if (wid == 0) {
                unsigned long long b2 = (lane < 8) ? s_part[lane] : 0ull;
                #pragma unroll
                for (int o = 4; o > 0; o >>= 1) {
                    unsigned long long ok = __shfl_down_sync(0xFFFFFFFFu, b2, o);
                    if (ok > b2) b2 = ok;
                }
                if (lane == 0) atomicMax(&g_best[it & 1][grp], b2);
            }
        }
        gsync_grp(grp);

        // ---- decode winner ----
        if (tid == 0) s_best = *((volatile unsigned long long*)&g_best[it & 1][grp]);
        __syncthreads();
        unsigned long long w = s_best;
        unsigned key = (unsigned)(w >> 32);
        unsigned uv = (key & 0x80000000u) ? (key & 0x7FFFFFFFu) : ~key;
        float v = __uint_as_float(uv);
        unsigned flat = 0xFFFFFFFFu - (unsigned)(w & 0xFFFFFFFFu);
        int n = (int)(flat >> 14);
        int t = (int)(flat & (T_LEN - 1));
        int L = min(t + ALEN, T_LEN - 1) - t;   // ref clips: position T-1 never written

        if (mem == 0) {
            // residual/recon update + reset idle-parity slot
            if (tid == 0) *((volatile unsigned long long*)&g_best[(it + 1) & 1][grp]) = 0ull;
            float* res = out + (size_t)grp * T_LEN;
            float* rec = out + (size_t)(BATCH + grp) * T_LEN;
            for (int u = tid; u < L; u += 256) {
                float wv = v * g_dn[n * ALEN + u];
                res[t + u] -= wv;
                rec[t + u] += wv;
            }
        }
        if (it == N_ITER - 1) return;

        if (L > 0) {
            int toff = t - (ALEN - 1);
            // build tf32 splits of the delta signal directly from g_dn
            for (int i = tid; i < SIGL; i += 256) {
                int j = i - (ALEN - 1);
                float sv = (j >= 0 && j < L) ? v * g_dn[n * ALEN + j] : 0.f;
                uint32_t big = f2tf32(sv);
                sS[i] = big;
                sS[SSL + i] = f2tf32(sv - __uint_as_float(big));
            }
            __syncthreads();

            #pragma unroll
            for (int pass = 0; pass < 2; pass++) {
                int tw = pass * 512 + wid * 64;
                int klo = max(0, (ALEN - 1) - (tw + 63)) & ~7;
                int khi = min(ALEN, (ALEN - 1) + L - tw);
                khi = (khi + 7) & ~7;
                if (klo >= khi) continue;

                float acc[2][8][4];
                #pragma unroll
                for (int mi = 0; mi < 2; mi++)
                    #pragma unroll
                    for (int ni = 0; ni < 8; ni++)
                        #pragma unroll
                        for (int q = 0; q < 4; q++) acc[mi][ni][q] = 0.f;

                for (int k0 = klo; k0 < khi; k0 += 8) {
                    int col = k0 + tig;
                    uint32_t Ab[2][4], As[2][4], Bb[8][2], Bs[8][2];
                    #pragma unroll
                    for (int mi = 0; mi < 2; mi++) {
                        const uint32_t* p = &sA[(mi * 16 + g) * KSTR + col];
                        Ab[mi][0] = p[0];
                        Ab[mi][1] = p[8 * KSTR];
                        Ab[mi][2] = p[4];
                        Ab[mi][3] = p[8 * KSTR + 4];
                        const uint32_t* q = p + 32 * KSTR;
                        As[mi][0] = q[0];
                        As[mi][1] = q[8 * KSTR];
                        As[mi][2] = q[4];
                        As[mi][3] = q[8 * KSTR + 4];
                    }
                    #pragma unroll
                    for (int ni = 0; ni < 8; ni++) {
                        int idx = tw + ni * 8 + g + col;
                        Bb[ni][0] = sS[idx];
                        Bb[ni][1] = sS[idx + 4];
                        Bs[ni][0] = sS[SSL + idx];
                        Bs[ni][1] = sS[SSL + idx + 4];
                    }
                    #pragma unroll
                    for (int mi = 0; mi < 2; mi++)
                        #pragma unroll
                        for (int ni = 0; ni < 8; ni++) {
                            mma8(acc[mi][ni], As[mi], Bb[ni]);
                            mma8(acc[mi][ni], Ab[mi], Bs[ni]);
                            mma8(acc[mi][ni], Ab[mi], Bb[ni]);
                        }
                }

                #pragma unroll
                for (int mi = 0; mi < 2; mi++) {
                    int n1 = n0 + mi * 16 + g;
                    float* row1 = g_fm + ((size_t)(grp * NATOMS + n1)) * T_LEN;
                    float* row2 = row1 + 8 * (size_t)T_LEN;
                    #pragma unroll
                    for (int ni = 0; ni < 8; ni++) {
                        int tt = toff + tw + ni * 8 + tig * 2;
                        if (tt >= 0 && tt < T_LEN)         row1[tt]     -= acc[mi][ni][0];
                        if (tt + 1 >= 0 && tt + 1 < T_LEN) row1[tt + 1] -= acc[mi][ni][1];
                        if (tt >= 0 && tt < T_LEN)         row2[tt]     -= acc[mi][ni][2];
                        if (tt + 1 >= 0 && tt + 1 < T_LEN) row2[tt + 1] -= acc[mi][ni][3];
                    }
                }
            }
            __syncthreads();   // all delta stores visible CTA-wide before refresh reads

            // ---- refresh own rows' touched block maxima (CTA-local fm) ----
            {
                int lo = max(0, t - (ALEN - 1));
                int hi = min(T_LEN - 1, t + (ALEN - 1));
                int bl0 = lo >> 10, bl1 = hi >> 10;
                for (int u = wid; u < 64; u += 8) {
                    int r = u >> 1;
                    int which = u & 1;
                    if (which && bl1 == bl0) continue;
                    int bl = which ? bl1 : bl0;
                    const float* row = &g_fm[((size_t)(grp * NATOMS + n0 + r)) * T_LEN + bl * BLKSZ];
                    float bv = -3.402823466e38f;
                    int bt = 0x7FFFFFFF;
                    #pragma unroll
                    for (int i = 0; i < 8; i++) {
                        int base = (i * 32 + lane) * 4;
                        float4 vv = *(const float4*)&row[base];
                        if (vv.x > bv) { bv = vv.x; bt = base; }
                        if (vv.y > bv) { bv = vv.y; bt = base + 1; }
                        if (vv.z > bv) { bv = vv.z; bt = base + 2; }
                        if (vv.w > bv) { bv = vv.w; bt = base + 3; }
                    }
                    #pragma unroll
                    for (int o = 16; o > 0; o >>= 1) {
                        float ov = __shfl_down_sync(0xFFFFFFFFu, bv, o);
                        int   ot = __shfl_down_sync(0xFFFFFFFFu, bt, o);
                        if (ov > bv || (ov == bv && ot < bt)) { bv = ov; bt = ot; }
                    }
                    if (lane == 0) {
                        int idx = (grp * NATOMS + n0 + r) * NBLK + bl;
                        g_bmax[idx] = bv;
                        g_barg[idx] = bl * BLKSZ + bt;
                    }
                }
            }
        }
        gsync_grp(grp);
    }
}

// ---------------- launch ----------------
extern "C" void kernel_launch(void* const* d_in, const int* in_sizes, int n_in,
                              void* d_out, int out_size) {
    const float* x = (const float*)d_in[0];
    const float* d = (const float*)d_in[1];
    float* out = (float*)d_out;

    cudaFuncSetAttribute(k_conv_full, cudaFuncAttributeMaxDynamicSharedMemorySize, SMEM_BYTES);
    cudaFuncSetAttribute(k_loop,      cudaFuncAttributeMaxDynamicSharedMemorySize, SMEM_BYTES);

    k_norm<<<NATOMS, 256>>>(d);
    k_prep<<<NATOMS, 256>>>();
    {
        int n = BATCH * T_LEN;
        k_init_out<<<(n + 255) / 256, 256>>>(x, out);
    }
    k_conv_full<<<dim3(T_LEN / TNP, NATOMS / TM, BATCH), 256, SMEM_BYTES>>>(x);
    k_bmax_init<<<dim3(NBLK, NATOMS, BATCH), 256>>>();
    k_loop<<<PCTAS, 256, SMEM_BYTES>>>(out);
}